// round 14
// baseline (speedup 1.0000x reference)
#include <cuda_runtime.h>
#include <math.h>

#define LAY 2
#define BB 64
#define HH 1024
#define TT 512
#define ON 1024
#define NBLK 128
#define NTHR 256
#define CH 128
#define ASZ (64*CH)
#define BSZ (32*CH)
#define GS 33
#define SMEMF (2*ASZ + 2*BSZ + BB*GS)
#define BH (BB*HH)

__device__ __align__(256) float g_h[2][LAY*BH];
__device__ __align__(256) float g_x0[BH];
__device__ unsigned g_gen, g_cnt;

// ---- XLA-replica nonlinearities ----
// XLA F32 tanh: |x| < 0.0004 -> x; else rational on x clamped to +-7.90531110763549805
__device__ __forceinline__ float tanh_xla(float x){
  float xc = fminf(fmaxf(x, -7.90531110763549805f), 7.90531110763549805f);
  float x2 = __fmul_rn(xc, xc);
  float p = -2.76076847742355e-16f;                 // alpha_13
  p = __fmaf_rn(x2, p,  2.00018790482477e-13f);     // alpha_11
  p = __fmaf_rn(x2, p, -8.60467152213735e-11f);     // alpha_9
  p = __fmaf_rn(x2, p,  5.12229709037114e-08f);     // alpha_7
  p = __fmaf_rn(x2, p,  1.48572235717979e-05f);     // alpha_5
  p = __fmaf_rn(x2, p,  6.37261928875436e-04f);     // alpha_3
  p = __fmaf_rn(x2, p,  4.89352455891786e-03f);     // alpha_1
  float num = __fmul_rn(xc, p);
  float q =  1.19825839466702e-06f;                 // beta_6
  q = __fmaf_rn(x2, q, 1.18534705686654e-04f);      // beta_4
  q = __fmaf_rn(x2, q, 2.26843463243900e-03f);      // beta_2
  q = __fmaf_rn(x2, q, 4.89352518554385e-03f);      // beta_0
  float r = __fdiv_rn(num, q);
  return (fabsf(x) < 0.0004f) ? x : r;
}
// XLA logistic expansion: sigmoid(x) = 0.5 + 0.5*tanh(0.5*x)
__device__ __forceinline__ float sigm_xla(float x){
  return __fadd_rn(0.5f, __fmul_rn(0.5f, tanh_xla(__fmul_rn(0.5f, x))));
}

// ---- cp.async staging (XOR-swizzled float4 columns) ----
__device__ __forceinline__ void cp16(float* d, const float* s){
  unsigned a=(unsigned)__cvta_generic_to_shared(d);
  asm volatile("cp.async.cg.shared.global [%0],[%1],16;\n"::"r"(a),"l"(s));
}
__device__ __forceinline__ void commit(){ asm volatile("cp.async.commit_group;\n":::"memory"); }
__device__ __forceinline__ void wait1(){ asm volatile("cp.async.wait_group 1;\n":::"memory"); }

__device__ __forceinline__ void cpA(float* dst, const float* src, int tid){
#pragma unroll
  for(int i=0;i<8;i++){
    int u = tid + i*NTHR, r = u>>5, c = u&31;
    cp16(dst + r*CH + ((c ^ (r&31))<<2), src + r*HH + (c<<2));
  }
}
__device__ __forceinline__ void cpBg(float* dst, const float* W, int jb, int koff, int tid){
#pragma unroll
  for(int i=0;i<4;i++){
    int u = tid + i*NTHR, r = u>>5, c = u&31;
    size_t gr = (size_t)((r>>3)*HH + jb + (r&7));
    cp16(dst + r*CH + ((c ^ r)<<2), W + gr*HH + koff + (c<<2));
  }
}
__device__ __forceinline__ void cpBf(float* dst, const float* W, int jb, int koff, int tid){
  int r = tid>>5, c = tid&31;
  cp16(dst + r*CH + ((c ^ r)<<2), W + (size_t)(jb+r)*HH + koff + (c<<2));
}

// ---- FFMA chunks with 2-way split accumulators (pairwise accumulation) ----
__device__ __forceinline__ void ffma_g(const float* As, const float* Bs,
                                       int v8, int n, float* acc){
  float c0[8], c1[8];
#pragma unroll
  for(int i=0;i<8;i++){ c0[i]=0.f; c1[i]=0.f; }
#pragma unroll
  for(int k4=0;k4<32;k4++){
    float* cc = (k4&1) ? c1 : c0;
    const float4 bv = *(const float4*)(Bs + n*CH + ((k4 ^ n)<<2));
#pragma unroll
    for(int i=0;i<8;i++){
      int b = v8 + i;
      const float4 av = *(const float4*)(As + b*CH + ((k4 ^ (b&31))<<2));
      cc[i] = __fmaf_rn(av.x, bv.x, cc[i]);
      cc[i] = __fmaf_rn(av.y, bv.y, cc[i]);
      cc[i] = __fmaf_rn(av.z, bv.z, cc[i]);
      cc[i] = __fmaf_rn(av.w, bv.w, cc[i]);
    }
  }
#pragma unroll
  for(int i=0;i<8;i++) acc[i] = __fadd_rn(acc[i], __fadd_rn(c0[i], c1[i]));
}
__device__ __forceinline__ void ffma_f(const float* As, const float* Bs,
                                       int b0, int j, float* a2){
  float d0[2]={0.f,0.f}, d1[2]={0.f,0.f};
#pragma unroll
  for(int k4=0;k4<32;k4++){
    float* dd = (k4&1) ? d1 : d0;
    const float4 bv = *(const float4*)(Bs + j*CH + ((k4 ^ j)<<2));
    const float4 a0 = *(const float4*)(As + b0*CH + ((k4 ^ (b0&31))<<2));
    const float4 a1 = *(const float4*)(As + (b0+32)*CH + ((k4 ^ (b0&31))<<2));
    dd[0] = __fmaf_rn(a0.x, bv.x, dd[0]); dd[0] = __fmaf_rn(a0.y, bv.y, dd[0]);
    dd[0] = __fmaf_rn(a0.z, bv.z, dd[0]); dd[0] = __fmaf_rn(a0.w, bv.w, dd[0]);
    dd[1] = __fmaf_rn(a1.x, bv.x, dd[1]); dd[1] = __fmaf_rn(a1.y, bv.y, dd[1]);
    dd[1] = __fmaf_rn(a1.z, bv.z, dd[1]); dd[1] = __fmaf_rn(a1.w, bv.w, dd[1]);
  }
  a2[0] = __fadd_rn(a2[0], __fadd_rn(d0[0], d1[0]));
  a2[1] = __fadd_rn(a2[1], __fadd_rn(d0[1], d1[1]));
}

__device__ __forceinline__ void grid_sync(unsigned* lgen){
  __syncthreads();
  if(threadIdx.x==0){
    unsigned tgt = ++(*lgen);
    __threadfence();
    if(atomicAdd(&g_cnt,1u)==NBLK-1u){
      atomicExch(&g_cnt,0u);
      __threadfence();
      atomicExch(&g_gen,tgt);
    } else {
      while(*(volatile unsigned*)&g_gen < tgt) __nanosleep(32);
      __threadfence();
    }
  }
  __syncthreads();
}

__global__ void lstm_init(const float* __restrict__ hidden, const float* __restrict__ iv){
  int n = blockIdx.x*blockDim.x + threadIdx.x;
  if(n < LAY*BH) g_h[0][n] = hidden[n];
  if(n < BH) g_x0[n] = iv[n & (HH-1)];
  if(n==0){ g_gen=0u; g_cnt=0u; }
}

__global__ void __launch_bounds__(NTHR,1) lstm_main(
  const float* __restrict__ cell, const float* __restrict__ W_ih, const float* __restrict__ W_hh,
  const float* __restrict__ b_ih, const float* __restrict__ b_hh,
  const float* __restrict__ fc_w, const float* __restrict__ fc_b, float* __restrict__ out)
{
  extern __shared__ float sm[];
  float* Ab[2] = {sm, sm+ASZ};
  float* Bb[2] = {sm+2*ASZ, sm+2*ASZ+BSZ};
  float* G = sm + 2*ASZ + 2*BSZ;

  const int tid=threadIdx.x, blk=blockIdx.x;
  const int lane=tid&31, wid=tid>>5;
  const int v8 = wid*8;
  const int fb0 = tid>>3;
  const int fj  = tid&7;
  const int jb = blk*8;

  // cell state in regs (l=0/1, slot k=0/1): slot idx = tid + k*256 -> (b=idx>>3, j=idx&7)
  float c0a, c0b, c1a, c1b;
  {
    int i0=tid, i1=tid+NTHR;
    c0a = cell[0*BH + (i0>>3)*HH + jb + (i0&7)];
    c0b = cell[0*BH + (i1>>3)*HH + jb + (i1&7)];
    c1a = cell[1*BH + (i0>>3)*HH + jb + (i0&7)];
    c1b = cell[1*BH + (i1>>3)*HH + jb + (i1&7)];
  }
  const float fcb = fc_b[jb + fj];

  unsigned lgen=0;
#pragma unroll 1
  for(int t=0;t<TT;t++){
    const int rb=t&1, wb=rb^1;
    const float* xin = (t==0) ? g_x0 : g_h[rb]+BH;
#pragma unroll 1
    for(int l=0;l<LAY;l++){
      const float* xa = (l==0) ? xin : g_h[wb];
      const float* ha = g_h[rb]+l*BH;
      const float* Wi = W_ih + (size_t)l*4*HH*HH;
      const float* Wh = W_hh + (size_t)l*4*HH*HH;

      cpA(Ab[0], xa, tid);    cpBg(Bb[0], Wi, jb, 0, tid);  commit();
      cpA(Ab[1], xa+CH, tid); cpBg(Bb[1], Wi, jb, CH, tid); commit();
      float acc[8] = {0,0,0,0,0,0,0,0};
      float sx[8];
#pragma unroll 1
      for(int c=0;c<16;c++){
        wait1(); __syncthreads();
        ffma_g(Ab[c&1], Bb[c&1], v8, lane, acc);
        if(c==7){
#pragma unroll
          for(int i=0;i<8;i++){ sx[i]=acc[i]; acc[i]=0.f; }  // S1 = x@W_ih^T done
        }
        __syncthreads();
        int c2=c+2;
        if(c2<16){
          int off=(c2&7)*CH;
          const float* A2 = (c2<8) ? xa : ha;
          const float* W2 = (c2<8) ? Wi : Wh;
          cpA(Ab[c2&1], A2+off, tid); cpBg(Bb[c2&1], W2, jb, off, tid);
        }
        commit();
      }
      // G = S1 + S2 (JAX order), bias added in combine
#pragma unroll
      for(int i=0;i<8;i++) G[(v8+i)*GS + lane] = __fadd_rn(sx[i], acc[i]);
      __syncthreads();

      const float* bi = b_ih + l*4*HH;
      const float* bh = b_hh + l*4*HH;
#pragma unroll
      for(int k=0;k<2;k++){
        int idx=tid+k*NTHR, b=idx>>3, j=idx&7;
        const float* Gr = G + b*GS;
        float big = bi[jb+j],        bhg = bh[jb+j];
        float bif = bi[HH+jb+j],     bhf = bh[HH+jb+j];
        float bigg= bi[2*HH+jb+j],   bhgg= bh[2*HH+jb+j];
        float bio = bi[3*HH+jb+j],   bho = bh[3*HH+jb+j];
        float ig = __fadd_rn(__fadd_rn(Gr[j],     big),  bhg);
        float fg = __fadd_rn(__fadd_rn(Gr[8+j],   bif),  bhf);
        float gg = __fadd_rn(__fadd_rn(Gr[16+j],  bigg), bhgg);
        float og = __fadd_rn(__fadd_rn(Gr[24+j],  bio),  bho);
        float cold = (l==0) ? (k==0 ? c0a : c0b) : (k==0 ? c1a : c1b);
        float sf = sigm_xla(fg), si = sigm_xla(ig), so = sigm_xla(og);
        float tg = tanh_xla(gg);
        float cn = __fadd_rn(__fmul_rn(sf, cold), __fmul_rn(si, tg));
        if(l==0){ if(k==0) c0a=cn; else c0b=cn; }
        else    { if(k==0) c1a=cn; else c1b=cn; }
        g_h[wb][l*BH + b*HH + jb + j] = __fmul_rn(so, tanh_xla(cn));
      }
      __syncthreads();
      grid_sync(&lgen);
    }

    // fc: out[:, t, jb..jb+7] = h1_new @ fc_w[jb..jb+7]^T + fc_b
    {
      const float* h1 = g_h[wb]+BH;
      cpA(Ab[0], h1, tid);    cpBf(Bb[0], fc_w, jb, 0, tid);  commit();
      cpA(Ab[1], h1+CH, tid); cpBf(Bb[1], fc_w, jb, CH, tid); commit();
      float a2[2] = {0,0};
#pragma unroll 1
      for(int c=0;c<8;c++){
        wait1(); __syncthreads();
        ffma_f(Ab[c&1], Bb[c&1], fb0, fj, a2);
        __syncthreads();
        int c2=c+2;
        if(c2<8){ cpA(Ab[c2&1], h1+c2*CH, tid); cpBf(Bb[c2&1], fc_w, jb, c2*CH, tid); }
        commit();
      }
      out[(size_t)fb0*TT*ON      + (size_t)t*ON + jb + fj] = __fadd_rn(a2[0], fcb);
      out[(size_t)(fb0+32)*TT*ON + (size_t)t*ON + jb + fj] = __fadd_rn(a2[1], fcb);
    }
  }
}

extern "C" void kernel_launch(void* const* d_in, const int* in_sizes, int n_in,
                              void* d_out, int out_size){
  const float* hidden=(const float*)d_in[0];
  const float* cell  =(const float*)d_in[1];
  const float* W_ih  =(const float*)d_in[2];
  const float* W_hh  =(const float*)d_in[3];
  const float* b_ih  =(const float*)d_in[4];
  const float* b_hh  =(const float*)d_in[5];
  const float* fc_w  =(const float*)d_in[6];
  const float* fc_b  =(const float*)d_in[7];
  const float* iv    =(const float*)d_in[8];
  float* out=(float*)d_out;
  cudaFuncSetAttribute(lstm_main, cudaFuncAttributeMaxDynamicSharedMemorySize, SMEMF*4);
  lstm_init<<<512,256>>>(hidden, iv);
  lstm_main<<<NBLK,NTHR,SMEMF*4>>>(cell,W_ih,W_hh,b_ih,b_hh,fc_w,fc_b,out);
}